// round 6
// baseline (speedup 1.0000x reference)
#include <cuda_runtime.h>
#include <math_constants.h>

#define NL 16384
#define NR 16384
#define CH 256
#define KNN 16

// ---------------- scratch (device globals; no allocation) ----------------
__device__ float4 g_refpack[NR];
__device__ int    g_idx[NL * KNN];
__device__ float  g_refK0[NR * CH];
__device__ float  g_refV0[NR * CH];
__device__ float  g_refK1[NR * CH];
__device__ float  g_refV1[NR * CH];
__device__ float  g_Q[NL * CH];
__device__ float  g_out0[NL * CH];
__device__ float  g_out1[NL * CH];
__device__ float  g_t[NL * CH];
__device__ float  g_u[NL * CH];
__device__ float  g_Wp[4][3][CH];   // pos_w @ {k0,v0,k1,v1}_w
__device__ float  g_cb[4][CH];      // pos_b @ w + b
__device__ float  g_ps[64 * CH];
__device__ float  g_pq[64 * CH];
__device__ float  g_scale[CH];
__device__ float  g_shift[CH];

// ---------------- pack refs: (x,y,z,|r|^2) ----------------
__global__ void pack_kernel(const float* __restrict__ refC) {
    int i = blockIdx.x * 256 + threadIdx.x;
    float x = refC[i * 3 + 0], y = refC[i * 3 + 1], z = refC[i * 3 + 2];
    g_refpack[i] = make_float4(x, y, z, x * x + y * y + z * z);
}

// ---------------- KNN: thread-per-query, smem tile scan ----------------
__device__ __forceinline__ void topk_insert(float (&v)[KNN], int (&id)[KNN], float cv, int ci) {
    v[KNN - 1] = cv; id[KNN - 1] = ci;
    #pragma unroll
    for (int j = KNN - 1; j > 0; --j) {
        if (v[j] < v[j - 1]) {   // strict < keeps ascending-index tie order (matches top_k)
            float tv = v[j]; v[j] = v[j - 1]; v[j - 1] = tv;
            int   ti = id[j]; id[j] = id[j - 1]; id[j - 1] = ti;
        }
    }
}

__global__ __launch_bounds__(128) void knn_kernel(const float* __restrict__ lossyC) {
    __shared__ float4 sm[1024];
    int q = blockIdx.x * 128 + threadIdx.x;
    float qx2 = -2.0f * lossyC[q * 3 + 0];
    float qy2 = -2.0f * lossyC[q * 3 + 1];
    float qz2 = -2.0f * lossyC[q * 3 + 2];
    float v[KNN]; int id[KNN];
    #pragma unroll
    for (int j = 0; j < KNN; j++) { v[j] = CUDART_INF_F; id[j] = 0; }

    for (int t = 0; t < NR; t += 1024) {
        __syncthreads();
        for (int j = threadIdx.x; j < 1024; j += 128) sm[j] = g_refpack[t + j];
        __syncthreads();
        for (int r = 0; r < 1024; r += 4) {
            float4 a = sm[r + 0], b = sm[r + 1], c = sm[r + 2], d = sm[r + 3];
            // val = |r|^2 - 2 q.r : exact fp32 integers -> exact tie semantics vs d2
            float c0 = fmaf(a.x, qx2, fmaf(a.y, qy2, fmaf(a.z, qz2, a.w)));
            float c1 = fmaf(b.x, qx2, fmaf(b.y, qy2, fmaf(b.z, qz2, b.w)));
            float c2 = fmaf(c.x, qx2, fmaf(c.y, qy2, fmaf(c.z, qz2, c.w)));
            float c3 = fmaf(d.x, qx2, fmaf(d.y, qy2, fmaf(d.z, qz2, d.w)));
            if (c0 < v[KNN - 1]) topk_insert(v, id, c0, t + r + 0);
            if (c1 < v[KNN - 1]) topk_insert(v, id, c1, t + r + 1);
            if (c2 < v[KNN - 1]) topk_insert(v, id, c2, t + r + 2);
            if (c3 < v[KNN - 1]) topk_insert(v, id, c3, t + r + 3);
        }
    }
    #pragma unroll
    for (int j = 0; j < KNN; j++) g_idx[q * KNN + j] = id[j];
}

// ---------------- tiny precompute: Wp = pos_w @ w, cb = pos_b @ w + b ----------------
__global__ void precompute_kernel(const float* __restrict__ p0w, const float* __restrict__ p0b,
                                  const float* __restrict__ p1w, const float* __restrict__ p1b,
                                  const float* __restrict__ k0w, const float* __restrict__ k0b,
                                  const float* __restrict__ v0w, const float* __restrict__ v0b,
                                  const float* __restrict__ k1w, const float* __restrict__ k1b,
                                  const float* __restrict__ v1w, const float* __restrict__ v1b) {
    int c = threadIdx.x;
    const float* pw[4] = {p0w, p0w, p1w, p1w};
    const float* pb[4] = {p0b, p0b, p1b, p1b};
    const float* w [4] = {k0w, v0w, k1w, v1w};
    const float* bb[4] = {k0b, v0b, k1b, v1b};
    for (int s = 0; s < 4; s++) {
        for (int r = 0; r < 3; r++) {
            float acc = 0.0f;
            for (int m = 0; m < CH; m++) acc = fmaf(pw[s][r * CH + m], w[s][m * CH + c], acc);
            g_Wp[s][r][c] = acc;
        }
        float acc = 0.0f;
        for (int m = 0; m < CH; m++) acc = fmaf(pb[s][m], w[s][m * CH + c], acc);
        g_cb[s][c] = acc + bb[s][c];
    }
}

// ---------------- fp32 SIMT GEMM: C[M,256] = A[M,256] @ B[256,256] (+bias) ----------------
#define BM 128
#define BN 128
#define BK 16
__global__ __launch_bounds__(256) void gemm_kernel(const float* __restrict__ A,
                                                   const float* __restrict__ B,
                                                   const float* __restrict__ bias,
                                                   float* __restrict__ Cout) {
    __shared__ float As[BK][BM + 4];
    __shared__ float Bs[BK][BN];
    const int tid = threadIdx.x;
    const int bm = blockIdx.x * BM;
    const int bn = blockIdx.y * BN;
    const int tx = tid & 15;
    const int ty = tid >> 4;
    float acc[8][8];
    #pragma unroll
    for (int i = 0; i < 8; i++)
        #pragma unroll
        for (int j = 0; j < 8; j++) acc[i][j] = 0.0f;

    for (int kk = 0; kk < CH; kk += BK) {
        #pragma unroll
        for (int u = 0; u < 2; u++) {
            int f = tid + u * 256;
            int row = f >> 2, kq = (f & 3) * 4;
            float4 a4 = *(const float4*)(A + (size_t)(bm + row) * CH + kk + kq);
            As[kq + 0][row] = a4.x; As[kq + 1][row] = a4.y;
            As[kq + 2][row] = a4.z; As[kq + 3][row] = a4.w;
            int kr = f >> 5, col = (f & 31) * 4;
            float4 b4 = *(const float4*)(B + (size_t)(kk + kr) * CH + bn + col);
            *(float4*)(&Bs[kr][col]) = b4;
        }
        __syncthreads();
        #pragma unroll
        for (int k = 0; k < BK; k++) {
            float a[8], b[8];
            *(float4*)(&a[0]) = *(const float4*)(&As[k][ty * 4]);
            *(float4*)(&a[4]) = *(const float4*)(&As[k][ty * 4 + 64]);
            *(float4*)(&b[0]) = *(const float4*)(&Bs[k][tx * 4]);
            *(float4*)(&b[4]) = *(const float4*)(&Bs[k][tx * 4 + 64]);
            #pragma unroll
            for (int i = 0; i < 8; i++)
                #pragma unroll
                for (int j = 0; j < 8; j++)
                    acc[i][j] = fmaf(a[i], b[j], acc[i][j]);
        }
        __syncthreads();
    }
    #pragma unroll
    for (int i = 0; i < 8; i++) {
        int row = bm + ((i < 4) ? (ty * 4 + i) : (64 + ty * 4 + i - 4));
        #pragma unroll
        for (int jh = 0; jh < 2; jh++) {
            int col = bn + jh * 64 + tx * 4;
            float4 o;
            o.x = acc[i][jh * 4 + 0]; o.y = acc[i][jh * 4 + 1];
            o.z = acc[i][jh * 4 + 2]; o.w = acc[i][jh * 4 + 3];
            if (bias) {
                o.x += bias[col + 0]; o.y += bias[col + 1];
                o.z += bias[col + 2]; o.w += bias[col + 3];
            }
            *(float4*)(Cout + (size_t)row * CH + col) = o;
        }
    }
}

// ---------------- attention: warp per query, fused pos-emb + gather ----------------
__global__ __launch_bounds__(128) void attn_kernel(const float* __restrict__ Q,
                                                   const float* __restrict__ lossyC,
                                                   float* __restrict__ out,
                                                   int layer) {
    const float* __restrict__ refK = layer ? g_refK1 : g_refK0;
    const float* __restrict__ refV = layer ? g_refV1 : g_refV0;
    const float* __restrict__ Wpk  = &g_Wp[2 * layer][0][0];
    const float* __restrict__ cbk  = g_cb[2 * layer];
    const float* __restrict__ Wpv  = &g_Wp[2 * layer + 1][0][0];
    const float* __restrict__ cbv  = g_cb[2 * layer + 1];

    const int lane = threadIdx.x & 31;
    const int warp = threadIdx.x >> 5;
    const int gw = blockIdx.x * 4 + warp;
    const int nwarps = gridDim.x * 4;

    float wpk[3][8], wpv[3][8], cbkr[8], cbvr[8];
    #pragma unroll
    for (int j = 0; j < 8; j++) {
        int c = lane + 32 * j;
        #pragma unroll
        for (int r = 0; r < 3; r++) {
            wpk[r][j] = Wpk[r * CH + c];
            wpv[r][j] = Wpv[r * CH + c];
        }
        cbkr[j] = cbk[c];
        cbvr[j] = cbv[c];
    }

    for (int n = gw; n < NL; n += nwarps) {
        float qx = lossyC[n * 3 + 0], qy = lossyC[n * 3 + 1], qz = lossyC[n * 3 + 2];
        float q[8];
        #pragma unroll
        for (int j = 0; j < 8; j++) q[j] = Q[(size_t)n * CH + lane + 32 * j];

        float lgt[KNN];
        #pragma unroll
        for (int k = 0; k < KNN; k++) {
            int i = g_idx[n * KNN + k];
            float4 rp = g_refpack[i];
            float rx = qx - rp.x, ry = qy - rp.y, rz = qz - rp.z;
            float dot = 0.0f;
            #pragma unroll
            for (int j = 0; j < 8; j++) {
                int c = lane + 32 * j;
                float km = refK[(size_t)i * CH + c];
                km = fmaf(rx, wpk[0][j], km);
                km = fmaf(ry, wpk[1][j], km);
                km = fmaf(rz, wpk[2][j], km);
                km += cbkr[j];
                dot = fmaf(km, q[j], dot);
            }
            #pragma unroll
            for (int o = 16; o > 0; o >>= 1) dot += __shfl_xor_sync(0xffffffffu, dot, o);
            lgt[k] = dot * 0.0625f;   // / sqrt(256)
        }
        float mx = lgt[0];
        #pragma unroll
        for (int k = 1; k < KNN; k++) mx = fmaxf(mx, lgt[k]);
        float s = 0.0f;
        #pragma unroll
        for (int k = 0; k < KNN; k++) { float e = __expf(lgt[k] - mx); lgt[k] = e; s += e; }
        float inv = 1.0f / s;

        float acc[8];
        #pragma unroll
        for (int j = 0; j < 8; j++) acc[j] = 0.0f;
        #pragma unroll
        for (int k = 0; k < KNN; k++) {
            int i = g_idx[n * KNN + k];
            float4 rp = g_refpack[i];
            float rx = qx - rp.x, ry = qy - rp.y, rz = qz - rp.z;
            float w = lgt[k] * inv;
            #pragma unroll
            for (int j = 0; j < 8; j++) {
                int c = lane + 32 * j;
                float vv = refV[(size_t)i * CH + c];
                vv = fmaf(rx, wpv[0][j], vv);
                vv = fmaf(ry, wpv[1][j], vv);
                vv = fmaf(rz, wpv[2][j], vv);
                vv += cbvr[j];
                acc[j] = fmaf(w, vv, acc[j]);
            }
        }
        #pragma unroll
        for (int j = 0; j < 8; j++) out[(size_t)n * CH + lane + 32 * j] = acc[j];
    }
}

// ---------------- BN: deterministic two-stage column stats ----------------
__global__ __launch_bounds__(256) void bn_part_kernel(const float* __restrict__ a,
                                                      const float* __restrict__ b) {
    int c = threadIdx.x;
    size_t base = (size_t)blockIdx.x * 256 * CH;
    float s = 0.0f, q = 0.0f;
    for (int r = 0; r < 256; r++) {
        float x = a[base + (size_t)r * CH + c];
        if (b) x += b[base + (size_t)r * CH + c];
        s += x;
        q = fmaf(x, x, q);
    }
    g_ps[blockIdx.x * CH + c] = s;
    g_pq[blockIdx.x * CH + c] = q;
}

__global__ void bn_fin_kernel(const float* __restrict__ g, const float* __restrict__ b) {
    int c = threadIdx.x;
    float s = 0.0f, q = 0.0f;
    for (int blk = 0; blk < 64; blk++) {
        s += g_ps[blk * CH + c];
        q += g_pq[blk * CH + c];
    }
    float m = s * (1.0f / NL);
    float var = q * (1.0f / NL) - m * m;
    float sc = rsqrtf(var + 1e-5f) * g[c];
    g_scale[c] = sc;
    g_shift[c] = b[c] - m * sc;
}

__global__ __launch_bounds__(1024) void bn_apply_kernel(const float* __restrict__ a,
                                                        const float* __restrict__ b,
                                                        float* __restrict__ out) {
    size_t i = (size_t)blockIdx.x * 1024 + threadIdx.x;
    int c = (int)(i & (CH - 1));
    float x = a[i];
    if (b) x += b[i];
    out[i] = fmaf(x, g_scale[c], g_shift[c]);
}

// ---------------- launch ----------------
extern "C" void kernel_launch(void* const* d_in, const int* in_sizes, int n_in,
                              void* d_out, int out_size) {
    const float* lossy_C = (const float*)d_in[0];
    const float* lossy_F = (const float*)d_in[1];
    const float* ref_C   = (const float*)d_in[2];
    const float* ref_F   = (const float*)d_in[3];
    const float* p0w = (const float*)d_in[4];  const float* p0b = (const float*)d_in[5];
    const float* p1w = (const float*)d_in[6];  const float* p1b = (const float*)d_in[7];
    const float* q0w = (const float*)d_in[8];  const float* q0b = (const float*)d_in[9];
    const float* k0w = (const float*)d_in[10]; const float* k0b = (const float*)d_in[11];
    const float* v0w = (const float*)d_in[12]; const float* v0b = (const float*)d_in[13];
    const float* q1w = (const float*)d_in[14]; const float* q1b = (const float*)d_in[15];
    const float* k1w = (const float*)d_in[16]; const float* k1b = (const float*)d_in[17];
    const float* v1w = (const float*)d_in[18]; const float* v1b = (const float*)d_in[19];
    const float* linw = (const float*)d_in[20]; const float* linb = (const float*)d_in[21];
    const float* bn0g = (const float*)d_in[22]; const float* bn0b = (const float*)d_in[23];
    const float* bn1g = (const float*)d_in[24]; const float* bn1b = (const float*)d_in[25];
    float* out = (float*)d_out;

    float *refK0, *refV0, *refK1, *refV1, *Qb, *o0, *o1, *tb, *ub;
    cudaGetSymbolAddress((void**)&refK0, g_refK0);
    cudaGetSymbolAddress((void**)&refV0, g_refV0);
    cudaGetSymbolAddress((void**)&refK1, g_refK1);
    cudaGetSymbolAddress((void**)&refV1, g_refV1);
    cudaGetSymbolAddress((void**)&Qb, g_Q);
    cudaGetSymbolAddress((void**)&o0, g_out0);
    cudaGetSymbolAddress((void**)&o1, g_out1);
    cudaGetSymbolAddress((void**)&tb, g_t);
    cudaGetSymbolAddress((void**)&ub, g_u);

    dim3 ggrid(NL / BM, CH / BN);

    pack_kernel<<<NR / 256, 256>>>(ref_C);
    knn_kernel<<<NL / 128, 128>>>(lossy_C);
    precompute_kernel<<<1, 256>>>(p0w, p0b, p1w, p1b, k0w, k0b, v0w, v0b, k1w, k1b, v1w, v1b);

    gemm_kernel<<<ggrid, 256>>>(ref_F, k0w, nullptr, refK0);
    gemm_kernel<<<ggrid, 256>>>(ref_F, v0w, nullptr, refV0);
    gemm_kernel<<<ggrid, 256>>>(ref_F, k1w, nullptr, refK1);
    gemm_kernel<<<ggrid, 256>>>(ref_F, v1w, nullptr, refV1);

    gemm_kernel<<<ggrid, 256>>>(lossy_F, q0w, q0b, Qb);
    attn_kernel<<<1024, 128>>>(Qb, lossy_C, o0, 0);

    gemm_kernel<<<ggrid, 256>>>(o0, q1w, q1b, Qb);
    attn_kernel<<<1024, 128>>>(Qb, lossy_C, o1, 1);

    // bn0(lossy_F + out) -> t
    bn_part_kernel<<<64, 256>>>(lossy_F, o1);
    bn_fin_kernel<<<1, 256>>>(bn0g, bn0b);
    bn_apply_kernel<<<NL * CH / 1024, 1024>>>(lossy_F, o1, tb);

    // lin
    gemm_kernel<<<ggrid, 256>>>(tb, linw, linb, ub);

    // bn1(u + t) -> out
    bn_part_kernel<<<64, 256>>>(ub, tb);
    bn_fin_kernel<<<1, 256>>>(bn1g, bn1b);
    bn_apply_kernel<<<NL * CH / 1024, 1024>>>(ub, tb, out);
}

// round 10
// speedup vs baseline: 1.2114x; 1.2114x over previous
#include <cuda_runtime.h>
#include <math_constants.h>

#define NL 16384
#define NR 16384
#define CH 256
#define KNN 16

// ---------------- scratch (device globals; no allocation) ----------------
__device__ float4 g_refpack[NR];
__device__ int    g_idx[NL * KNN];
__device__ float  g_refK0[NR * CH];
__device__ float  g_refV0[NR * CH];
__device__ float  g_refK1[NR * CH];
__device__ float  g_refV1[NR * CH];
__device__ float  g_Q[NL * CH];
__device__ float  g_out0[NL * CH];
__device__ float  g_out1[NL * CH];
__device__ float  g_t[NL * CH];
__device__ float  g_u[NL * CH];
__device__ float  g_Wp[4][3][CH];   // pos_w @ {k0,v0,k1,v1}_w
__device__ float  g_cb[4][CH];      // pos_b @ w + b
__device__ float  g_ps[64 * CH];
__device__ float  g_pq[64 * CH];
__device__ float  g_scale[CH];
__device__ float  g_shift[CH];

// ---------------- pack refs: (x,y,z,|r|^2) ----------------
__global__ void pack_kernel(const float* __restrict__ refC) {
    int i = blockIdx.x * 256 + threadIdx.x;
    float x = refC[i * 3 + 0], y = refC[i * 3 + 1], z = refC[i * 3 + 2];
    g_refpack[i] = make_float4(x, y, z, x * x + y * y + z * z);
}

// ---------------- KNN v2: 64 queries/block, 4 stripes/query ----------------
__device__ __forceinline__ void topk_insert(float (&v)[KNN], int (&id)[KNN], float cv, int ci) {
    v[KNN - 1] = cv; id[KNN - 1] = ci;
    #pragma unroll
    for (int j = KNN - 1; j > 0; --j) {
        if (v[j] < v[j - 1]) {   // strict < keeps ascending-index tie order (matches top_k)
            float tv = v[j]; v[j] = v[j - 1]; v[j - 1] = tv;
            int   ti = id[j]; id[j] = id[j - 1]; id[j - 1] = ti;
        }
    }
}

__global__ __launch_bounds__(256) void knn_kernel(const float* __restrict__ lossyC) {
    __shared__ float4 sm[512];              // phase tile: 512 refs
    __shared__ float  s_val[4][64][KNN];    // per-stripe partial top-16 values
    __shared__ int    s_idx[4][64][KNN];    // per-stripe partial top-16 indices

    const int ql     = threadIdx.x & 63;    // local query 0..63
    const int stripe = threadIdx.x >> 6;    // 0..3
    const int q      = blockIdx.x * 64 + ql;

    const float qx2 = -2.0f * lossyC[q * 3 + 0];
    const float qy2 = -2.0f * lossyC[q * 3 + 1];
    const float qz2 = -2.0f * lossyC[q * 3 + 2];

    float v[KNN]; int id[KNN];
    #pragma unroll
    for (int j = 0; j < KNN; j++) { v[j] = CUDART_INF_F; id[j] = 0; }

    // Phase m covers refs [m*512, m*512+512). Stripe s scans sub-block
    // [m*512 + s*128, +128). Stripe's global indices are strictly increasing
    // across phases -> per-stripe list keeps top_k tie semantics.
    for (int m = 0; m < 32; m++) {
        __syncthreads();
        int base = m * 512;
        sm[threadIdx.x]       = g_refpack[base + threadIdx.x];
        sm[threadIdx.x + 256] = g_refpack[base + threadIdx.x + 256];
        __syncthreads();

        const float4* my = &sm[stripe * 128];
        int gbase = base + stripe * 128;
        for (int r = 0; r < 128; r += 4) {
            float4 a = my[r + 0], b = my[r + 1], c = my[r + 2], d = my[r + 3];
            // val = |r|^2 - 2 q.r : exact fp32 integers -> exact tie semantics
            float c0 = fmaf(a.x, qx2, fmaf(a.y, qy2, fmaf(a.z, qz2, a.w)));
            float c1 = fmaf(b.x, qx2, fmaf(b.y, qy2, fmaf(b.z, qz2, b.w)));
            float c2 = fmaf(c.x, qx2, fmaf(c.y, qy2, fmaf(c.z, qz2, c.w)));
            float c3 = fmaf(d.x, qx2, fmaf(d.y, qy2, fmaf(d.z, qz2, d.w)));
            if (c0 < v[KNN - 1]) topk_insert(v, id, c0, gbase + r + 0);
            if (c1 < v[KNN - 1]) topk_insert(v, id, c1, gbase + r + 1);
            if (c2 < v[KNN - 1]) topk_insert(v, id, c2, gbase + r + 2);
            if (c3 < v[KNN - 1]) topk_insert(v, id, c3, gbase + r + 3);
        }
    }

    #pragma unroll
    for (int j = 0; j < KNN; j++) {
        s_val[stripe][ql][j] = v[j];
        s_idx[stripe][ql][j] = id[j];
    }
    __syncthreads();

    // 4-way merge by (val, idx) lexicographic -> exact top_k order.
    if (threadIdx.x < 64) {
        int p[4] = {0, 0, 0, 0};
        #pragma unroll
        for (int j = 0; j < KNN; j++) {
            float bv = s_val[0][threadIdx.x][p[0]];
            int   bi = s_idx[0][threadIdx.x][p[0]];
            int   bs = 0;
            #pragma unroll
            for (int s = 1; s < 4; s++) {
                float cv = s_val[s][threadIdx.x][p[s]];
                int   ci = s_idx[s][threadIdx.x][p[s]];
                if (cv < bv || (cv == bv && ci < bi)) { bv = cv; bi = ci; bs = s; }
            }
            g_idx[(blockIdx.x * 64 + threadIdx.x) * KNN + j] = bi;
            p[bs]++;
        }
    }
}

// ---------------- tiny precompute: Wp = pos_w @ w, cb = pos_b @ w + b ----------------
__global__ void precompute_kernel(const float* __restrict__ p0w, const float* __restrict__ p0b,
                                  const float* __restrict__ p1w, const float* __restrict__ p1b,
                                  const float* __restrict__ k0w, const float* __restrict__ k0b,
                                  const float* __restrict__ v0w, const float* __restrict__ v0b,
                                  const float* __restrict__ k1w, const float* __restrict__ k1b,
                                  const float* __restrict__ v1w, const float* __restrict__ v1b) {
    int c = threadIdx.x;
    const float* pw[4] = {p0w, p0w, p1w, p1w};
    const float* pb[4] = {p0b, p0b, p1b, p1b};
    const float* w [4] = {k0w, v0w, k1w, v1w};
    const float* bb[4] = {k0b, v0b, k1b, v1b};
    for (int s = 0; s < 4; s++) {
        for (int r = 0; r < 3; r++) {
            float acc = 0.0f;
            for (int m = 0; m < CH; m++) acc = fmaf(pw[s][r * CH + m], w[s][m * CH + c], acc);
            g_Wp[s][r][c] = acc;
        }
        float acc = 0.0f;
        for (int m = 0; m < CH; m++) acc = fmaf(pb[s][m], w[s][m * CH + c], acc);
        g_cb[s][c] = acc + bb[s][c];
    }
}

// ---------------- fp32 SIMT GEMM: C[M,256] = A[M,256] @ B[256,256] (+bias) ----------------
#define BM 128
#define BN 128
#define BK 16
__global__ __launch_bounds__(256) void gemm_kernel(const float* __restrict__ A,
                                                   const float* __restrict__ B,
                                                   const float* __restrict__ bias,
                                                   float* __restrict__ Cout) {
    __shared__ float As[BK][BM + 4];
    __shared__ float Bs[BK][BN];
    const int tid = threadIdx.x;
    const int bm = blockIdx.x * BM;
    const int bn = blockIdx.y * BN;
    const int tx = tid & 15;
    const int ty = tid >> 4;
    float acc[8][8];
    #pragma unroll
    for (int i = 0; i < 8; i++)
        #pragma unroll
        for (int j = 0; j < 8; j++) acc[i][j] = 0.0f;

    for (int kk = 0; kk < CH; kk += BK) {
        #pragma unroll
        for (int u = 0; u < 2; u++) {
            int f = tid + u * 256;
            int row = f >> 2, kq = (f & 3) * 4;
            float4 a4 = *(const float4*)(A + (size_t)(bm + row) * CH + kk + kq);
            As[kq + 0][row] = a4.x; As[kq + 1][row] = a4.y;
            As[kq + 2][row] = a4.z; As[kq + 3][row] = a4.w;
            int kr = f >> 5, col = (f & 31) * 4;
            float4 b4 = *(const float4*)(B + (size_t)(kk + kr) * CH + bn + col);
            *(float4*)(&Bs[kr][col]) = b4;
        }
        __syncthreads();
        #pragma unroll
        for (int k = 0; k < BK; k++) {
            float a[8], b[8];
            *(float4*)(&a[0]) = *(const float4*)(&As[k][ty * 4]);
            *(float4*)(&a[4]) = *(const float4*)(&As[k][ty * 4 + 64]);
            *(float4*)(&b[0]) = *(const float4*)(&Bs[k][tx * 4]);
            *(float4*)(&b[4]) = *(const float4*)(&Bs[k][tx * 4 + 64]);
            #pragma unroll
            for (int i = 0; i < 8; i++)
                #pragma unroll
                for (int j = 0; j < 8; j++)
                    acc[i][j] = fmaf(a[i], b[j], acc[i][j]);
        }
        __syncthreads();
    }
    #pragma unroll
    for (int i = 0; i < 8; i++) {
        int row = bm + ((i < 4) ? (ty * 4 + i) : (64 + ty * 4 + i - 4));
        #pragma unroll
        for (int jh = 0; jh < 2; jh++) {
            int col = bn + jh * 64 + tx * 4;
            float4 o;
            o.x = acc[i][jh * 4 + 0]; o.y = acc[i][jh * 4 + 1];
            o.z = acc[i][jh * 4 + 2]; o.w = acc[i][jh * 4 + 3];
            if (bias) {
                o.x += bias[col + 0]; o.y += bias[col + 1];
                o.z += bias[col + 2]; o.w += bias[col + 3];
            }
            *(float4*)(Cout + (size_t)row * CH + col) = o;
        }
    }
}

// ---------------- attention v2: one query per warp, 8 warps/block ----------------
__global__ __launch_bounds__(256) void attn_kernel(const float* __restrict__ Q,
                                                   const float* __restrict__ lossyC,
                                                   float* __restrict__ out,
                                                   int layer) {
    const float* __restrict__ refK = layer ? g_refK1 : g_refK0;
    const float* __restrict__ refV = layer ? g_refV1 : g_refV0;
    const float* __restrict__ Wpk  = &g_Wp[2 * layer][0][0];
    const float* __restrict__ cbk  = g_cb[2 * layer];
    const float* __restrict__ Wpv  = &g_Wp[2 * layer + 1][0][0];
    const float* __restrict__ cbv  = g_cb[2 * layer + 1];

    const int lane = threadIdx.x & 31;
    const int warp = threadIdx.x >> 5;
    const int n = blockIdx.x * 8 + warp;    // grid = NL/8 = 2048

    float wpk[3][8], cbkr[8];
    #pragma unroll
    for (int j = 0; j < 8; j++) {
        int c = lane + 32 * j;
        #pragma unroll
        for (int r = 0; r < 3; r++) wpk[r][j] = Wpk[r * CH + c];
        cbkr[j] = cbk[c];
    }

    const float qx = lossyC[n * 3 + 0], qy = lossyC[n * 3 + 1], qz = lossyC[n * 3 + 2];
    float q[8];
    #pragma unroll
    for (int j = 0; j < 8; j++) q[j] = Q[(size_t)n * CH + lane + 32 * j];

    int nb[KNN];
    #pragma unroll
    for (int k = 0; k < KNN; k++) nb[k] = g_idx[n * KNN + k];

    float lgt[KNN];
    #pragma unroll
    for (int k = 0; k < KNN; k++) {
        int i = nb[k];
        float4 rp = g_refpack[i];
        float rx = qx - rp.x, ry = qy - rp.y, rz = qz - rp.z;
        float dot = 0.0f;
        #pragma unroll
        for (int j = 0; j < 8; j++) {
            int c = lane + 32 * j;
            float km = refK[(size_t)i * CH + c];
            km = fmaf(rx, wpk[0][j], km);
            km = fmaf(ry, wpk[1][j], km);
            km = fmaf(rz, wpk[2][j], km);
            km += cbkr[j];
            dot = fmaf(km, q[j], dot);
        }
        #pragma unroll
        for (int o = 16; o > 0; o >>= 1) dot += __shfl_xor_sync(0xffffffffu, dot, o);
        lgt[k] = dot * 0.0625f;   // / sqrt(256)
    }
    float mx = lgt[0];
    #pragma unroll
    for (int k = 1; k < KNN; k++) mx = fmaxf(mx, lgt[k]);
    float s = 0.0f;
    #pragma unroll
    for (int k = 0; k < KNN; k++) { float e = __expf(lgt[k] - mx); lgt[k] = e; s += e; }
    float inv = 1.0f / s;

    float wpv[3][8], cbvr[8];
    #pragma unroll
    for (int j = 0; j < 8; j++) {
        int c = lane + 32 * j;
        #pragma unroll
        for (int r = 0; r < 3; r++) wpv[r][j] = Wpv[r * CH + c];
        cbvr[j] = cbv[c];
    }

    float acc[8];
    #pragma unroll
    for (int j = 0; j < 8; j++) acc[j] = 0.0f;
    #pragma unroll
    for (int k = 0; k < KNN; k++) {
        int i = nb[k];
        float4 rp = g_refpack[i];
        float rx = qx - rp.x, ry = qy - rp.y, rz = qz - rp.z;
        float w = lgt[k] * inv;
        #pragma unroll
        for (int j = 0; j < 8; j++) {
            int c = lane + 32 * j;
            float vv = refV[(size_t)i * CH + c];
            vv = fmaf(rx, wpv[0][j], vv);
            vv = fmaf(ry, wpv[1][j], vv);
            vv = fmaf(rz, wpv[2][j], vv);
            vv += cbvr[j];
            acc[j] = fmaf(w, vv, acc[j]);
        }
    }
    #pragma unroll
    for (int j = 0; j < 8; j++) out[(size_t)n * CH + lane + 32 * j] = acc[j];
}

// ---------------- BN: deterministic two-stage column stats ----------------
__global__ __launch_bounds__(256) void bn_part_kernel(const float* __restrict__ a,
                                                      const float* __restrict__ b) {
    int c = threadIdx.x;
    size_t base = (size_t)blockIdx.x * 256 * CH;
    float s = 0.0f, q = 0.0f;
    for (int r = 0; r < 256; r++) {
        float x = a[base + (size_t)r * CH + c];
        if (b) x += b[base + (size_t)r * CH + c];
        s += x;
        q = fmaf(x, x, q);
    }
    g_ps[blockIdx.x * CH + c] = s;
    g_pq[blockIdx.x * CH + c] = q;
}

__global__ void bn_fin_kernel(const float* __restrict__ g, const float* __restrict__ b) {
    int c = threadIdx.x;
    float s = 0.0f, q = 0.0f;
    for (int blk = 0; blk < 64; blk++) {
        s += g_ps[blk * CH + c];
        q += g_pq[blk * CH + c];
    }
    float m = s * (1.0f / NL);
    float var = q * (1.0f / NL) - m * m;
    float sc = rsqrtf(var + 1e-5f) * g[c];
    g_scale[c] = sc;
    g_shift[c] = b[c] - m * sc;
}

__global__ __launch_bounds__(1024) void bn_apply_kernel(const float* __restrict__ a,
                                                        const float* __restrict__ b,
                                                        float* __restrict__ out) {
    size_t i = (size_t)blockIdx.x * 1024 + threadIdx.x;
    int c = (int)(i & (CH - 1));
    float x = a[i];
    if (b) x += b[i];
    out[i] = fmaf(x, g_scale[c], g_shift[c]);
}

// ---------------- launch ----------------
extern "C" void kernel_launch(void* const* d_in, const int* in_sizes, int n_in,
                              void* d_out, int out_size) {
    const float* lossy_C = (const float*)d_in[0];
    const float* lossy_F = (const float*)d_in[1];
    const float* ref_C   = (const float*)d_in[2];
    const float* ref_F   = (const float*)d_in[3];
    const float* p0w = (const float*)d_in[4];  const float* p0b = (const float*)d_in[5];
    const float* p1w = (const float*)d_in[6];  const float* p1b = (const float*)d_in[7];
    const float* q0w = (const float*)d_in[8];  const float* q0b = (const float*)d_in[9];
    const float* k0w = (const float*)d_in[10]; const float* k0b = (const float*)d_in[11];
    const float* v0w = (const float*)d_in[12]; const float* v0b = (const float*)d_in[13];
    const float* q1w = (const float*)d_in[14]; const float* q1b = (const float*)d_in[15];
    const float* k1w = (const float*)d_in[16]; const float* k1b = (const float*)d_in[17];
    const float* v1w = (const float*)d_in[18]; const float* v1b = (const float*)d_in[19];
    const float* linw = (const float*)d_in[20]; const float* linb = (const float*)d_in[21];
    const float* bn0g = (const float*)d_in[22]; const float* bn0b = (const float*)d_in[23];
    const float* bn1g = (const float*)d_in[24]; const float* bn1b = (const float*)d_in[25];
    float* out = (float*)d_out;

    float *refK0, *refV0, *refK1, *refV1, *Qb, *o0, *o1, *tb, *ub;
    cudaGetSymbolAddress((void**)&refK0, g_refK0);
    cudaGetSymbolAddress((void**)&refV0, g_refV0);
    cudaGetSymbolAddress((void**)&refK1, g_refK1);
    cudaGetSymbolAddress((void**)&refV1, g_refV1);
    cudaGetSymbolAddress((void**)&Qb, g_Q);
    cudaGetSymbolAddress((void**)&o0, g_out0);
    cudaGetSymbolAddress((void**)&o1, g_out1);
    cudaGetSymbolAddress((void**)&tb, g_t);
    cudaGetSymbolAddress((void**)&ub, g_u);

    dim3 ggrid(NL / BM, CH / BN);

    pack_kernel<<<NR / 256, 256>>>(ref_C);
    knn_kernel<<<NL / 64, 256>>>(lossy_C);
    precompute_kernel<<<1, 256>>>(p0w, p0b, p1w, p1b, k0w, k0b, v0w, v0b, k1w, k1b, v1w, v1b);

    gemm_kernel<<<ggrid, 256>>>(ref_F, k0w, nullptr, refK0);
    gemm_kernel<<<ggrid, 256>>>(ref_F, v0w, nullptr, refV0);
    gemm_kernel<<<ggrid, 256>>>(ref_F, k1w, nullptr, refK1);
    gemm_kernel<<<ggrid, 256>>>(ref_F, v1w, nullptr, refV1);

    gemm_kernel<<<ggrid, 256>>>(lossy_F, q0w, q0b, Qb);
    attn_kernel<<<NL / 8, 256>>>(Qb, lossy_C, o0, 0);

    gemm_kernel<<<ggrid, 256>>>(o0, q1w, q1b, Qb);
    attn_kernel<<<NL / 8, 256>>>(Qb, lossy_C, o1, 1);

    // bn0(lossy_F + out) -> t
    bn_part_kernel<<<64, 256>>>(lossy_F, o1);
    bn_fin_kernel<<<1, 256>>>(bn0g, bn0b);
    bn_apply_kernel<<<NL * CH / 1024, 1024>>>(lossy_F, o1, tb);

    // lin
    gemm_kernel<<<ggrid, 256>>>(tb, linw, linb, ub);

    // bn1(u + t) -> out
    bn_part_kernel<<<64, 256>>>(ub, tb);
    bn_fin_kernel<<<1, 256>>>(bn1g, bn1b);
    bn_apply_kernel<<<NL * CH / 1024, 1024>>>(ub, tb, out);
}